// round 5
// baseline (speedup 1.0000x reference)
#include <cuda_runtime.h>
#include <cstdint>

#define BB 32
#define JJ 256
#define MM 128
#define DD 200
#define NTH 512
#define CH 50            // d-chunk per rank
#define CSZ 4            // cluster size
#define MP 53            // padded mem chunk row stride (conflict-free column walks)

// ---------------- persistent transposed weight scratch (fp32) ----------------
__device__ __align__(16) float g_wTg[400 * 800];   // [k][4*d+g], k<200 ih else hh
__device__ __align__(16) float g_wTfc1[400 * 200]; // [k][d], k: x then q
__device__ __align__(16) float g_wTfc[200 * 200];  // [k][d]
__device__ __align__(16) float g_bg[800];          // b_ih+b_hh gate-interleaved

__global__ void prep_kernel(const float* __restrict__ w_fc, const float* __restrict__ w_fc1,
                            const float* __restrict__ w_ih, const float* __restrict__ w_hh,
                            const float* __restrict__ b_ih, const float* __restrict__ b_hh)
{
    int stride = gridDim.x * blockDim.x;
    int i0 = blockIdx.x * blockDim.x + threadIdx.x;

    for (int idx = i0; idx < 400 * 800; idx += stride) {
        int k = idx / 800, rem = idx % 800;
        int d = rem >> 2, g = rem & 3;
        int o = g * 200 + d;
        g_wTg[idx] = (k < 200) ? w_ih[o * 200 + k] : w_hh[o * 200 + (k - 200)];
    }
    for (int idx = i0; idx < 800; idx += stride) {
        int d = idx >> 2, g = idx & 3;
        int o = g * 200 + d;
        g_bg[idx] = b_ih[o] + b_hh[o];
    }
    for (int idx = i0; idx < 400 * 200; idx += stride) {
        int k = idx / 200, d = idx % 200;
        g_wTfc1[idx] = w_fc1[d * 400 + k];
    }
    for (int idx = i0; idx < 200 * 200; idx += stride) {
        int k = idx / 200, d = idx % 200;
        g_wTfc[idx] = w_fc[d * 200 + k];
    }
}

__device__ __forceinline__ float sigf(float v) { return 1.0f / (1.0f + __expf(-v)); }
__device__ __forceinline__ float ftanh(float x) { return 1.0f - 2.0f / (__expf(2.0f * x) + 1.0f); }

__device__ __forceinline__ void cluster_bar()
{
    asm volatile("barrier.cluster.arrive.aligned;\n\t"
                 "barrier.cluster.wait.aligned;" ::: "memory");
}
__device__ __forceinline__ void st_peer(uint32_t laddr, uint32_t peer, float v)
{
    uint32_t r;
    asm volatile("mapa.shared::cluster.u32 %0, %1, %2;" : "=r"(r) : "r"(laddr), "r"(peer));
    asm volatile("st.shared::cluster.f32 [%0], %1;" :: "r"(r), "f"(v) : "memory");
}
__device__ __forceinline__ void st_peer_v4(uint32_t laddr, uint32_t peer, float4 v)
{
    uint32_t r;
    unsigned long long lo = (unsigned long long)__float_as_uint(v.x) |
                            ((unsigned long long)__float_as_uint(v.y) << 32);
    unsigned long long hi = (unsigned long long)__float_as_uint(v.z) |
                            ((unsigned long long)__float_as_uint(v.w) << 32);
    asm volatile("mapa.shared::cluster.u32 %0, %1, %2;" : "=r"(r) : "r"(laddr), "r"(peer));
    asm volatile("st.shared::cluster.b64 [%0], %1;" :: "r"(r), "l"(lo) : "memory");
    asm volatile("st.shared::cluster.b64 [%0+8], %1;" :: "r"(r), "l"(hi) : "memory");
}
// release-arrive on a PEER CTA's mbarrier (publishes this thread's prior cluster stores)
__device__ __forceinline__ void arrive_peer(uint32_t lbar, uint32_t peer)
{
    uint32_t r;
    asm volatile("mapa.shared::cluster.u32 %0, %1, %2;" : "=r"(r) : "r"(lbar), "r"(peer));
    asm volatile("mbarrier.arrive.release.cluster.shared::cluster.b64 _, [%0];"
                 :: "r"(r) : "memory");
}
__device__ __forceinline__ void mbar_init(uint32_t bar, uint32_t count)
{
    asm volatile("mbarrier.init.shared.b64 [%0], %1;" :: "r"(bar), "r"(count) : "memory");
}
__device__ __forceinline__ void mbar_wait_cl(uint32_t bar, uint32_t parity)
{
    asm volatile(
        "{\n\t.reg .pred P1;\n\t"
        "WAIT_%=:\n\t"
        "mbarrier.try_wait.parity.acquire.cluster.shared::cta.b64 P1, [%0], %1, 0x989680;\n\t"
        "@P1 bra.uni DONE_%=;\n\t"
        "bra.uni WAIT_%=;\n\t"
        "DONE_%=:\n\t}"
        :: "r"(bar), "r"(parity) : "memory");
}

// ---------------- SMEM layout (float indices) ----------------
#define SM_MEM   0                      // mem[2][128][MP] = 13568
#define SM_GP    13568                  // gparts[4 src][200] = 800
#define SM_ATTP  14368                  // attp[4][128] = 512
#define SM_QP    14880                  // qparts[4][50] = 200
#define SM_ZP    15080                  // zparts[4][50] = 200
#define SM_PART  15280                  // part scratch 1600
#define SM_ATT   16880                  // att[128]
#define SM_RED   17008                  // red[8]
#define SM_XV    17016                  // xv[56]
#define SM_CS    17072                  // cstage[2][128]
#define SM_BJ    17328                  // bstage[2][200]
#define SM_QL    17728                  // qloc[56]
#define SM_HL    17784                  // hloc[56]
#define SM_CV    17840                  // cvec[56]
#define SM_BG    17896                  // bgs[224]
#define SM_BFC   18120                  // bfcs[56]
#define SM_BFC1  18176                  // bfc1s[56]
#define SM_MB    18232                  // 4 mbarriers (u64) = 8 floats (8B aligned)
#define SM_TOT   18240                  // 72960 bytes

// mbarrier arrive counts (remote-arriving threads per consumer)
#define CNT_G 150
#define CNT_A 384
#define CNT_Q 150
#define CNT_Z 150

__global__ void __launch_bounds__(NTH, 1) __cluster_dims__(CSZ, 1, 1)
speaker_kernel(const float* __restrict__ cosp, const float* __restrict__ bank,
               const float* __restrict__ mem_a, const float* __restrict__ mem_b,
               const float* __restrict__ b_fc, const float* __restrict__ b_fc1,
               float* __restrict__ out)
{
    extern __shared__ float sm[];
    float* smem_mem = sm + SM_MEM;
    float* gparts = sm + SM_GP;
    float* attp   = sm + SM_ATTP;
    float* qparts = sm + SM_QP;
    float* zparts = sm + SM_ZP;
    float* part   = sm + SM_PART;
    float* att    = sm + SM_ATT;
    float* red    = sm + SM_RED;
    float* xv     = sm + SM_XV;
    float* cstage = sm + SM_CS;
    float* bstage = sm + SM_BJ;
    float* qloc   = sm + SM_QL;
    float* hloc   = sm + SM_HL;
    float* cvec   = sm + SM_CV;
    float* bgs    = sm + SM_BG;
    float* bfcs   = sm + SM_BFC;
    float* bfc1s  = sm + SM_BFC1;

    const int tid  = threadIdx.x;
    const int lane = blockIdx.x >> 2;
    const uint32_t rank = blockIdx.x & 3;
    const int cbase = (int)rank * CH;
    const uint32_t sb = (uint32_t)__cvta_generic_to_shared(sm);
    const uint32_t mb_g = sb + 4u * SM_MB;
    const uint32_t mb_a = mb_g + 8;
    const uint32_t mb_q = mb_g + 16;
    const uint32_t mb_z = mb_g + 24;

    // ---- init barriers, biases, mem chunks, first-step staging ----
    if (tid == 0) {
        mbar_init(mb_g, CNT_G);
        mbar_init(mb_a, CNT_A);
        mbar_init(mb_q, CNT_Q);
        mbar_init(mb_z, CNT_Z);
    }
    if (tid < 224) bgs[tid] = g_bg[rank * 200 + min(tid, 199)];
    if (tid < CH) { bfcs[tid] = b_fc[cbase + tid]; bfc1s[tid] = b_fc1[cbase + tid]; }
    if (tid < MM) cstage[tid] = cosp[(lane * JJ + 0) * MM + tid];
    if (tid < DD) bstage[tid] = bank[(0 * BB + lane) * DD + tid];
    for (int idx = tid; idx < MM * CH; idx += NTH) {
        int m = idx / CH, d = idx % CH;
        smem_mem[m * MP + d]           = mem_a[lane * MM * DD + m * DD + cbase + d];
        smem_mem[MM * MP + m * MP + d] = mem_b[lane * MM * DD + m * DD + cbase + d];
    }
    __syncthreads();
    cluster_bar();    // mbarrier inits visible cluster-wide before any remote arrive

    uint32_t gu = 0, au = 0, qu = 0, zu = 0;   // barrier use counters (parity)

    for (int j = 0; j < JJ; ++j) {
        const int flag = j & 1;
        const int slot = j >> 1;
        float* mem = smem_mem + flag * (MM * MP);
        const float* csj = cstage + (j & 1) * MM;
        const float* bjj = bstage + (j & 1) * DD;

        // ---- P1: q-init partials (col-split) + h-init chunk partials ----
        if (tid < 400) {
            int ks = tid / 50, c = tid % 50;
            int k0 = ks * 25;
            float a = 0.f;
            const float* W = g_wTfc + cbase + c;
            #pragma unroll 5
            for (int i = 0; i < 25; ++i) a += bjj[k0 + i] * W[(k0 + i) * 200];
            part[ks * 50 + c] = a;
        } else if (tid < 500) {
            int t = tid - 400, seg = t / 50, d = t % 50;
            float a = 0.f;
            const float* mp = mem + (seg * 64) * MP + d;
            #pragma unroll 8
            for (int m = 0; m < 64; ++m) a += csj[seg * 64 + m] * mp[m * MP];
            part[400 + seg * 50 + d] = a;
        }
        __syncthreads();
        // ---- P2: combine q / combine h / reset c ----
        if (tid < CH) {
            float a = bfcs[tid];
            #pragma unroll
            for (int ks = 0; ks < 8; ++ks) a += part[ks * 50 + tid];
            qloc[tid] = a;
        } else if (tid >= 64 && tid < 64 + CH) {
            int t = tid - 64;
            hloc[t] = part[400 + t] + part[450 + t];
        } else if (tid >= 128 && tid < 128 + CH) {
            cvec[tid - 128] = 0.0f;
        }
        __syncthreads();

        // ---------------- inner loop P=3 ----------------
        for (int p = 0; p < 3; ++p) {
            // G0: gates partials k-local (streaming __ldcs); idle threads prefetch next stage
            if (tid < 400) {
                int ks = tid / 200, c = tid % 200;
                const float4* W4 = reinterpret_cast<const float4*>(g_wTg)
                                   + (ks ? (200 + cbase) : cbase) * 200 + c;
                const float* act = ks ? hloc : qloc;
                float4 acc = make_float4(0.f, 0.f, 0.f, 0.f);
                #pragma unroll 10
                for (int i = 0; i < CH; ++i) {
                    float v = act[i];
                    float4 w = __ldcs(&W4[i * 200]);
                    acc.x += v * w.x; acc.y += v * w.y; acc.z += v * w.z; acc.w += v * w.w;
                }
                reinterpret_cast<float4*>(part)[ks * 200 + c] = acc;
            } else if (p == 0 && j + 1 < JJ) {
                int nj = j + 1, nb = nj & 1;
                for (int i = tid - 400; i < MM; i += 112)
                    cstage[nb * MM + i] = cosp[(lane * JJ + nj) * MM + i];
                for (int i = tid - 400; i < DD; i += 112)
                    bstage[nb * DD + i] = bank[(nj * BB + lane) * DD + i];
            }
            __syncthreads();
            // G0b: combine ks + deposit quad to owner (+ remote arrive)
            if (tid < 200) {
                const float4* p4 = reinterpret_cast<const float4*>(part);
                float4 a = p4[tid], b = p4[200 + tid];
                float4 v = make_float4(a.x + b.x, a.y + b.y, a.z + b.z, a.w + b.w);
                int owner = tid / CH, cq = tid % CH;
                uint32_t off = SM_GP + rank * 200 + cq * 4;
                if (owner == (int)rank) {
                    *reinterpret_cast<float4*>(sm + off) = v;
                } else {
                    st_peer_v4(sb + 4u * off, (uint32_t)owner, v);
                    arrive_peer(mb_g, (uint32_t)owner);
                }
            }
            __syncthreads();
            if (tid < 224) mbar_wait_cl(mb_g, gu & 1);
            gu++;
            // G1: reduce 4 sources + LSTM (quad-parallel activations)
            if (tid < 224) {
                int t = min(tid, 199);
                int chl = t >> 2, gi = t & 3;
                float g = bgs[t];
                #pragma unroll
                for (int s = 0; s < 4; ++s) g += gparts[s * 200 + chl * 4 + gi];
                float val = (gi == 2) ? ftanh(g) : sigf(g);
                float ig = __shfl_sync(0xffffffffu, val, 0, 4);
                float fg = __shfl_sync(0xffffffffu, val, 1, 4);
                float gg = __shfl_sync(0xffffffffu, val, 2, 4);
                float og = __shfl_sync(0xffffffffu, val, 3, 4);
                if (tid < 200 && gi == 0) {
                    float cc = fg * cvec[chl] + ig * gg;
                    cvec[chl] = cc;
                    hloc[chl] = og * ftanh(cc);
                }
            }
            __syncthreads();
            // G2: attention logit partials over local d-chunk
            if (tid < 256) {
                int m = tid & 127, hf = tid >> 7;
                float a = 0.f;
                const float* mrow = mem + m * MP + hf * 25;
                const float* hseg = hloc + hf * 25;
                #pragma unroll 5
                for (int i = 0; i < 25; ++i) a += hseg[i] * mrow[i];
                part[hf * 128 + m] = a;
            }
            __syncthreads();
            // G2b: push logit partials to all peers (+ arrive per peer)
            if (tid < 128) {
                float a = part[tid] + part[128 + tid];
                uint32_t off = SM_ATTP + rank * 128 + tid;
                sm[off] = a;
                #pragma unroll
                for (uint32_t pr = 1; pr < CSZ; ++pr) {
                    uint32_t peer = (rank + pr) & 3;
                    st_peer(sb + 4u * off, peer, a);
                    arrive_peer(mb_a, peer);
                }
            }
            __syncthreads();
            if (tid < 32) mbar_wait_cl(mb_a, au & 1);
            au++;
            // G3: single-warp softmax (combine, max, exp, sum)
            if (tid < 32) {
                float v0 = attp[tid]       + attp[128 + tid]       + attp[256 + tid]       + attp[384 + tid];
                float v1 = attp[tid + 32]  + attp[160 + tid]       + attp[288 + tid]       + attp[416 + tid];
                float v2 = attp[tid + 64]  + attp[192 + tid]       + attp[320 + tid]       + attp[448 + tid];
                float v3 = attp[tid + 96]  + attp[224 + tid]       + attp[352 + tid]       + attp[480 + tid];
                float mx = fmaxf(fmaxf(v0, v1), fmaxf(v2, v3));
                #pragma unroll
                for (int o = 16; o > 0; o >>= 1) mx = fmaxf(mx, __shfl_xor_sync(0xffffffffu, mx, o));
                float e0 = __expf(v0 - mx), e1 = __expf(v1 - mx);
                float e2 = __expf(v2 - mx), e3 = __expf(v3 - mx);
                float s = e0 + e1 + e2 + e3;
                #pragma unroll
                for (int o = 16; o > 0; o >>= 1) s += __shfl_xor_sync(0xffffffffu, s, o);
                att[tid] = e0; att[tid + 32] = e1; att[tid + 64] = e2; att[tid + 96] = e3;
                if (tid == 0) red[0] = 1.0f / s;
            }
            __syncthreads();
            // G5: x chunk partials (8 m-segs x 50 d)
            if (tid < 400) {
                int seg = tid / 50, d = tid % 50;
                float a = 0.f;
                const float* mp = mem + (seg * 16) * MP + d;
                #pragma unroll 8
                for (int m = 0; m < 16; ++m) a += att[seg * 16 + m] * mp[m * MP];
                part[seg * 50 + d] = a;
            }
            __syncthreads();
            if (tid < CH) {
                float a = 0.f;
                #pragma unroll
                for (int s = 0; s < 8; ++s) a += part[s * 50 + tid];
                xv[tid] = a * red[0];
            }
            __syncthreads();
            // G6: fc1 partials, k-local
            if (tid < 400) {
                int ks = tid / 200, c = tid % 200;
                const float* W = g_wTfc1 + (ks ? (200 + cbase) : cbase) * 200 + c;
                const float* act = ks ? qloc : xv;
                float a = 0.f;
                #pragma unroll 10
                for (int i = 0; i < CH; ++i) a += act[i] * W[i * 200];
                part[ks * 200 + c] = a;
            }
            __syncthreads();
            // G6b: deposit q partials to owner (+ arrive)
            if (tid < 200) {
                float v = part[tid] + part[200 + tid];
                int owner = tid / CH;
                uint32_t off = SM_QP + rank * CH + (tid % CH);
                if (owner == (int)rank) {
                    sm[off] = v;
                } else {
                    st_peer(sb + 4u * off, (uint32_t)owner, v);
                    arrive_peer(mb_q, (uint32_t)owner);
                }
            }
            __syncthreads();
            if (tid < 64) mbar_wait_cl(mb_q, qu & 1);
            qu++;
            // G7: q chunk reduce
            if (tid < CH) {
                float a = bfc1s[tid];
                #pragma unroll
                for (int s = 0; s < 4; ++s) a += qparts[s * CH + tid];
                qloc[tid] = a;
            }
            __syncthreads();
        }

        // ---- epilogue ----
        if (tid < 400) {
            int ks = tid / 200, c = tid % 200;
            const float* W = g_wTfc + (cbase + ks * 25) * 200 + c;
            const float* svp = mem + slot * MP + ks * 25;
            const float* qp  = qloc + ks * 25;
            float a = 0.f;
            #pragma unroll 5
            for (int i = 0; i < 25; ++i) a += (qp[i] + svp[i]) * W[i * 200];
            part[ks * 200 + c] = a;
        } else if (tid >= 448 && tid < 448 + CH) {
            int t = tid - 448;
            out[(lane * JJ + j) * DD + cbase + t] = qloc[t];
        }
        __syncthreads();
        if (tid < 200) {
            float v = part[tid] + part[200 + tid];
            int owner = tid / CH;
            uint32_t off = SM_ZP + rank * CH + (tid % CH);
            if (owner == (int)rank) {
                sm[off] = v;
            } else {
                st_peer(sb + 4u * off, (uint32_t)owner, v);
                arrive_peer(mb_z, (uint32_t)owner);
            }
        }
        __syncthreads();
        if (tid < 64) mbar_wait_cl(mb_z, zu & 1);
        zu++;
        if (tid < CH) {
            float a = 2.0f * bfcs[tid];
            #pragma unroll
            for (int s = 0; s < 4; ++s) a += zparts[s * CH + tid];
            float z = tanhf(a);
            mem[slot * MP + tid] *= z;
        }
        __syncthreads();
    }
}

extern "C" void kernel_launch(void* const* d_in, const int* in_sizes, int n_in,
                              void* d_out, int out_size)
{
    const float* cosp  = (const float*)d_in[0];
    const float* bank  = (const float*)d_in[1];
    const float* mem_a = (const float*)d_in[2];
    const float* mem_b = (const float*)d_in[3];
    const float* w_fc  = (const float*)d_in[4];
    const float* b_fc  = (const float*)d_in[5];
    const float* w_fc1 = (const float*)d_in[6];
    const float* b_fc1 = (const float*)d_in[7];
    const float* w_ih  = (const float*)d_in[8];
    const float* w_hh  = (const float*)d_in[9];
    const float* b_ih  = (const float*)d_in[10];
    const float* b_hh  = (const float*)d_in[11];
    float* out = (float*)d_out;

    prep_kernel<<<148, 256>>>(w_fc, w_fc1, w_ih, w_hh, b_ih, b_hh);

    size_t smem_bytes = SM_TOT * sizeof(float);
    cudaFuncSetAttribute(speaker_kernel, cudaFuncAttributeMaxDynamicSharedMemorySize,
                         (int)smem_bytes);
    speaker_kernel<<<BB * CSZ, NTH, smem_bytes>>>(cosp, bank, mem_a, mem_b, b_fc, b_fc1, out);
}